// round 15
// baseline (speedup 1.0000x reference)
#include <cuda_runtime.h>

typedef unsigned long long ull;

static constexpr int T_STEPS = 64;
static constexpr int NSIDE = 256;
static constexpr int NPTS = NSIDE * NSIDE;   // 65536
static constexpr int HID = 32;
static constexpr int BLK = 128;
static constexpr float LOG2E = 1.44269504088896340736f;

// Constant bank (MUST stay <= ~4.6KB: larger footprints miss the const cache
// to L2 -- measured cliff R12 vs R10/R11/R13): SECOND half of W1 (cc 16..31),
// folded biases, W2.
struct CW {
    ull w1b[HID * 16];    // [jj*16 + (cc-16)] = dup(log2e*W1[cc][jj])
    ull b1[HID];          // dup(log2e*(b1[jj] - sum_c W1[c][jj]))
    ull w2[HID];          // dup(W2[jj])
    float b2;             // b2 - sum_j W2[j]
};
__constant__ CW cw;
__device__ CW g_stage;

__device__ __forceinline__ ull dupf(float v) {
    unsigned u = __float_as_uint(v);
    return (ull)u | ((ull)u << 32);
}

__global__ void prep_kernel(const float* __restrict__ W1, const float* __restrict__ b1,
                            const float* __restrict__ W2, const float* __restrict__ b2) {
    const int tid = threadIdx.x;
    for (int i0 = tid; i0 < HID * 16; i0 += BLK) {
        int jj = i0 >> 4, cc = (i0 & 15) + 16;
        g_stage.w1b[i0] = dupf(LOG2E * W1[cc * HID + jj]);
    }
    if (tid < HID) {
        float s = 0.0f;
        for (int c = 0; c < HID; c++) s += W1[c * HID + tid];
        g_stage.b1[tid] = dupf(LOG2E * (b1[tid] - s));
        g_stage.w2[tid] = dupf(W2[tid]);
    }
    if (tid == 0) {
        float s = 0.0f;
        for (int jj = 0; jj < HID; jj++) s += W2[jj];
        g_stage.b2 = b2[0] - s;
    }
}

// ---- packed f32x2 helpers (Blackwell FFMA2 only reachable via PTX) ----
__device__ __forceinline__ ull fma2(ull a, ull b, ull c) {
    ull d;
    asm("fma.rn.f32x2 %0, %1, %2, %3;" : "=l"(d) : "l"(a), "l"(b), "l"(c));
    return d;
}
__device__ __forceinline__ ull mul2(ull a, ull b) {
    ull d;
    asm("mul.rn.f32x2 %0, %1, %2;" : "=l"(d) : "l"(a), "l"(b));
    return d;
}
__device__ __forceinline__ ull add2(ull a, ull b) {
    ull d;
    asm("add.rn.f32x2 %0, %1, %2;" : "=l"(d) : "l"(a), "l"(b));
    return d;
}
__device__ __forceinline__ ull pk2(float lo, float hi) {
    ull r;
    asm("mov.b64 %0, {%1, %2};" : "=l"(r) : "f"(lo), "f"(hi));
    return r;
}
__device__ __forceinline__ void upk2(ull v, float& lo, float& hi) {
    asm("mov.b64 {%0, %1}, %2;" : "=f"(lo), "=f"(hi) : "l"(v));
}
__device__ __forceinline__ float ex2f(float v) {
    float r;
    asm("ex2.approx.f32 %0, %1;" : "=f"(r) : "f"(v));
    return r;
}
// preactivation pre-scaled by log2e:  g(v) = elu(v)+1 = max(v',0)*ln2 + ex2(min(v',0))
__device__ __forceinline__ ull g2(ull v) {
    const float LN2 = 0.69314718055994530942f;
    float a, b; upk2(v, a, b);
    float ea = ex2f(fminf(a, 0.0f));
    float eb = ex2f(fminf(b, 0.0f));
    float ha = fmaf(fmaxf(a, 0.0f), LN2, ea);
    float hb = fmaf(fmaxf(b, 0.0f), LN2, eb);
    return pk2(ha, hb);
}

// 2 consecutive points per thread as ONE f32x2 pair. DUAL-PORT weights:
// layer0 + W1 lower half from SMEM (L1 port), W1 upper half + biases from the
// constant bank (constant port, under the const-cache cliff).
// 96-reg cap -> 5 blocks x 128 threads per SM (20 warps, 5 per SMSP).
__global__ __launch_bounds__(BLK, 5)
void mlpconv_kernel(const float* __restrict__ x,
                    const float* __restrict__ W0, const float* __restrict__ b0,
                    const float* __restrict__ W1,
                    float* __restrict__ out) {
    // sW0r[jj][0..4] = dup(log2e*W0[c][jj]), [5] = dup(log2e*b0[jj]), pad to 8
    __shared__ __align__(16) ull sW0r[HID * 8];
    // sW1a[jj*16+cc] = dup(log2e*W1[cc][jj]) for cc 0..15
    __shared__ __align__(16) ull sW1a[HID * 16];

    const int tid = threadIdx.x;

    for (int i0 = tid; i0 < HID * 16; i0 += BLK) {
        int jj = i0 >> 4, cc = i0 & 15;
        sW1a[i0] = dupf(LOG2E * W1[cc * HID + jj]);
    }
    for (int i0 = tid; i0 < HID * 8; i0 += BLK) {
        int jj = i0 >> 3, c = i0 & 7;
        float v = 0.0f;
        if (c < 5)       v = LOG2E * W0[c * HID + jj];
        else if (c == 5) v = LOG2E * b0[jj];
        sW0r[i0] = dupf(v);
    }
    __syncthreads();

    const int gid = blockIdx.x * BLK + tid;
    const int base = gid * 2;                  // 2 points per thread
    const int t = base >> 16;
    const int p = base & (NPTS - 1);
    const float* xt = x + ((size_t)t << 16);
    const int i = p >> 8;
    const int j = p & 255;                     // even -> pair never crosses a row

    // Stencil (reference's exact wrap semantics)
    const float2 c2 = *reinterpret_cast<const float2*>(xt + p);
    const float2 u2 = *reinterpret_cast<const float2*>(xt + ((p - NSIDE) & (NPTS - 1)));
    const float2 d2 = *reinterpret_cast<const float2*>(xt + ((p + NSIDE) & (NPTS - 1)));
    const float lE = xt[(p - 1) & (NPTS - 1)];
    const float rE = xt[(i << 8) | ((j + 2) & 255)];

    // channel order: l, l2(up), c, r, r2(down); halves = points (0,1)
    const ull pxl = pk2(lE,   c2.x);
    const ull pxu = pk2(u2.x, u2.y);
    const ull pxc = pk2(c2.x, c2.y);
    const ull pxr = pk2(c2.y, rE);
    const ull pxd = pk2(d2.x, d2.y);

    // ---- layer 0: [5] -> [32], SMEM weights, g-activation (2 chains) ----
    ull h0[HID];
#pragma unroll
    for (int jj = 0; jj < HID; jj++) {
        const ulonglong2* r = reinterpret_cast<const ulonglong2*>(sW0r + jj * 8);
        ulonglong2 w01 = r[0];
        ulonglong2 w23 = r[1];
        ulonglong2 w4b = r[2];
        ull a0 = fma2(pxl, w01.x, w4b.y);
        ull a1 = mul2(pxu, w01.y);
        a0 = fma2(pxc, w23.x, a0);
        a1 = fma2(pxr, w23.y, a1);
        a0 = fma2(pxd, w4b.x, a0);
        h0[jj] = g2(add2(a0, a1));
    }

    // ---- layer 1: [32] -> [32], g-activation, fused layer-2 accumulation ----
    // chain a0 consumes SMEM weights (cc 0..15), chain a1 consumes constant
    // weights (cc 16..31): the two load ports run in parallel.
    ull oA = pk2(cw.b2, cw.b2);
    ull oB = pk2(0.0f, 0.0f);
#pragma unroll
    for (int jj = 0; jj < HID; jj++) {
        const ulonglong2* rs = reinterpret_cast<const ulonglong2*>(sW1a + jj * 16);
        const ull* rc = cw.w1b + jj * 16;
        ulonglong2 w = rs[0];
        ull a0 = fma2(h0[0], w.x, cw.b1[jj]);
        ull a1 = mul2(h0[16], rc[0]);
        a0 = fma2(h0[1], w.y, a0);
        a1 = fma2(h0[17], rc[1], a1);
#pragma unroll
        for (int k = 1; k < 8; k++) {
            w = rs[k];
            a0 = fma2(h0[2 * k],      w.x,           a0);
            a1 = fma2(h0[16 + 2 * k], rc[2 * k],     a1);
            a0 = fma2(h0[2 * k + 1],  w.y,           a0);
            a1 = fma2(h0[17 + 2 * k], rc[2 * k + 1], a1);
        }
        ull a = g2(add2(a0, a1));
        if (jj & 1) oB = fma2(a, cw.w2[jj], oB);
        else        oA = fma2(a, cw.w2[jj], oA);
    }
    ull o = add2(oA, oB);

    float o0, o1;
    upk2(o, o0, o1);
    *reinterpret_cast<float2*>(out + base) = make_float2(o0, o1);
}

extern "C" void kernel_launch(void* const* d_in, const int* in_sizes, int n_in,
                              void* d_out, int out_size) {
    const float* x  = (const float*)d_in[0];
    const float* W0 = (const float*)d_in[1];
    const float* b0 = (const float*)d_in[2];
    const float* W1 = (const float*)d_in[3];
    const float* b1 = (const float*)d_in[4];
    const float* W2 = (const float*)d_in[5];
    const float* b2 = (const float*)d_in[6];
    float* out = (float*)d_out;

    // 1) fold/transform the constant-bank half into staging (device global)
    prep_kernel<<<1, BLK>>>(W1, b1, W2, b2);

    // 2) staging -> constant bank (D2D async memcpy, graph-capturable)
    void* stage_ptr = nullptr;
    cudaGetSymbolAddress(&stage_ptr, g_stage);
    cudaMemcpyToSymbolAsync(cw, stage_ptr, sizeof(CW), 0, cudaMemcpyDeviceToDevice, 0);

    // 3) main kernel (stages SMEM halves itself)
    const int total = T_STEPS * NPTS;       // 4194304 points
    const int threads = total / 2;          // 2 points per thread
    mlpconv_kernel<<<threads / BLK, BLK>>>(x, W0, b0, W1, out);
}

// round 16
// speedup vs baseline: 1.0332x; 1.0332x over previous
#include <cuda_runtime.h>

typedef unsigned long long ull;

static constexpr int T_STEPS = 64;
static constexpr int NSIDE = 256;
static constexpr int NPTS = NSIDE * NSIDE;   // 65536
static constexpr int HID = 32;
static constexpr int BLK = 128;
static constexpr float LOG2E = 1.44269504088896340736f;

// Constant bank (MUST stay <= ~4.6KB: larger footprints miss the const cache
// to L2 -- measured cliff R12 vs R10/R11/R13): SECOND half of W1 (cc 16..31),
// folded biases, W2. 16B-aligned for LDC.128 fetches.
struct CW {
    ull w1b[HID * 16];    // [jj*16 + (cc-16)] = dup(log2e*W1[cc][jj])
    ull b1[HID];          // dup(log2e*(b1[jj] - sum_c W1[c][jj]))
    ull w2[HID];          // dup(W2[jj])
    float b2;             // b2 - sum_j W2[j]
};
__constant__ __align__(16) CW cw;
__device__ __align__(16) CW g_stage;

__device__ __forceinline__ ull dupf(float v) {
    unsigned u = __float_as_uint(v);
    return (ull)u | ((ull)u << 32);
}

__global__ void prep_kernel(const float* __restrict__ W1, const float* __restrict__ b1,
                            const float* __restrict__ W2, const float* __restrict__ b2) {
    const int tid = threadIdx.x;
    for (int i0 = tid; i0 < HID * 16; i0 += BLK) {
        int jj = i0 >> 4, cc = (i0 & 15) + 16;
        g_stage.w1b[i0] = dupf(LOG2E * W1[cc * HID + jj]);
    }
    if (tid < HID) {
        float s = 0.0f;
        for (int c = 0; c < HID; c++) s += W1[c * HID + tid];
        g_stage.b1[tid] = dupf(LOG2E * (b1[tid] - s));
        g_stage.w2[tid] = dupf(W2[tid]);
    }
    if (tid == 0) {
        float s = 0.0f;
        for (int jj = 0; jj < HID; jj++) s += W2[jj];
        g_stage.b2 = b2[0] - s;
    }
}

// ---- packed f32x2 helpers (Blackwell FFMA2 only reachable via PTX) ----
__device__ __forceinline__ ull fma2(ull a, ull b, ull c) {
    ull d;
    asm("fma.rn.f32x2 %0, %1, %2, %3;" : "=l"(d) : "l"(a), "l"(b), "l"(c));
    return d;
}
__device__ __forceinline__ ull mul2(ull a, ull b) {
    ull d;
    asm("mul.rn.f32x2 %0, %1, %2;" : "=l"(d) : "l"(a), "l"(b));
    return d;
}
__device__ __forceinline__ ull add2(ull a, ull b) {
    ull d;
    asm("add.rn.f32x2 %0, %1, %2;" : "=l"(d) : "l"(a), "l"(b));
    return d;
}
__device__ __forceinline__ ull pk2(float lo, float hi) {
    ull r;
    asm("mov.b64 %0, {%1, %2};" : "=l"(r) : "f"(lo), "f"(hi));
    return r;
}
__device__ __forceinline__ void upk2(ull v, float& lo, float& hi) {
    asm("mov.b64 {%0, %1}, %2;" : "=f"(lo), "=f"(hi) : "l"(v));
}
__device__ __forceinline__ float ex2f(float v) {
    float r;
    asm("ex2.approx.f32 %0, %1;" : "=f"(r) : "f"(v));
    return r;
}
// preactivation pre-scaled by log2e:  g(v) = elu(v)+1 = max(v',0)*ln2 + ex2(min(v',0))
__device__ __forceinline__ ull g2(ull v) {
    const float LN2 = 0.69314718055994530942f;
    float a, b; upk2(v, a, b);
    float ea = ex2f(fminf(a, 0.0f));
    float eb = ex2f(fminf(b, 0.0f));
    float ha = fmaf(fmaxf(a, 0.0f), LN2, ea);
    float hb = fmaf(fmaxf(b, 0.0f), LN2, eb);
    return pk2(ha, hb);
}

// 2 consecutive points per thread as ONE f32x2 pair. DUAL-PORT weights:
// layer0 + W1 lower half from SMEM (L1 port, LDS.128), W1 upper half + biases
// from the constant bank (constant port, LDC.128, under the const-cache
// cliff). 128 regs -> 4 blocks x 128 threads per SM.
__global__ __launch_bounds__(BLK, 4)
void mlpconv_kernel(const float* __restrict__ x,
                    const float* __restrict__ W0, const float* __restrict__ b0,
                    const float* __restrict__ W1,
                    float* __restrict__ out) {
    // sW0r[jj][0..4] = dup(log2e*W0[c][jj]), [5] = dup(log2e*b0[jj]), pad to 8
    __shared__ __align__(16) ull sW0r[HID * 8];
    // sW1a[jj*16+cc] = dup(log2e*W1[cc][jj]) for cc 0..15
    __shared__ __align__(16) ull sW1a[HID * 16];

    const int tid = threadIdx.x;

    for (int i0 = tid; i0 < HID * 16; i0 += BLK) {
        int jj = i0 >> 4, cc = i0 & 15;
        sW1a[i0] = dupf(LOG2E * W1[cc * HID + jj]);
    }
    for (int i0 = tid; i0 < HID * 8; i0 += BLK) {
        int jj = i0 >> 3, c = i0 & 7;
        float v = 0.0f;
        if (c < 5)       v = LOG2E * W0[c * HID + jj];
        else if (c == 5) v = LOG2E * b0[jj];
        sW0r[i0] = dupf(v);
    }
    __syncthreads();

    const int gid = blockIdx.x * BLK + tid;
    const int base = gid * 2;                  // 2 points per thread
    const int t = base >> 16;
    const int p = base & (NPTS - 1);
    const float* xt = x + ((size_t)t << 16);
    const int i = p >> 8;
    const int j = p & 255;                     // even -> pair never crosses a row

    // Stencil (reference's exact wrap semantics)
    const float2 c2 = *reinterpret_cast<const float2*>(xt + p);
    const float2 u2 = *reinterpret_cast<const float2*>(xt + ((p - NSIDE) & (NPTS - 1)));
    const float2 d2 = *reinterpret_cast<const float2*>(xt + ((p + NSIDE) & (NPTS - 1)));
    const float lE = xt[(p - 1) & (NPTS - 1)];
    const float rE = xt[(i << 8) | ((j + 2) & 255)];

    // channel order: l, l2(up), c, r, r2(down); halves = points (0,1)
    const ull pxl = pk2(lE,   c2.x);
    const ull pxu = pk2(u2.x, u2.y);
    const ull pxc = pk2(c2.x, c2.y);
    const ull pxr = pk2(c2.y, rE);
    const ull pxd = pk2(d2.x, d2.y);

    // ---- layer 0: [5] -> [32], SMEM weights, g-activation (2 chains) ----
    ull h0[HID];
#pragma unroll
    for (int jj = 0; jj < HID; jj++) {
        const ulonglong2* r = reinterpret_cast<const ulonglong2*>(sW0r + jj * 8);
        ulonglong2 w01 = r[0];
        ulonglong2 w23 = r[1];
        ulonglong2 w4b = r[2];
        ull a0 = fma2(pxl, w01.x, w4b.y);
        ull a1 = mul2(pxu, w01.y);
        a0 = fma2(pxc, w23.x, a0);
        a1 = fma2(pxr, w23.y, a1);
        a0 = fma2(pxd, w4b.x, a0);
        h0[jj] = g2(add2(a0, a1));
    }

    // ---- layer 1: [32] -> [32], g-activation, fused layer-2 accumulation ----
    // chain a0 consumes SMEM weights (LDS.128, cc 0..15), chain a1 consumes
    // constant weights (LDC.128, cc 16..31): both ports, wide loads.
    ull oA = pk2(cw.b2, cw.b2);
    ull oB = pk2(0.0f, 0.0f);
#pragma unroll
    for (int jj = 0; jj < HID; jj++) {
        const ulonglong2* rs = reinterpret_cast<const ulonglong2*>(sW1a + jj * 16);
        const ulonglong2* rc = reinterpret_cast<const ulonglong2*>(cw.w1b + jj * 16);
        ulonglong2 ws = rs[0];
        ulonglong2 wc = rc[0];
        ull a0 = fma2(h0[0], ws.x, cw.b1[jj]);
        ull a1 = mul2(h0[16], wc.x);
        a0 = fma2(h0[1], ws.y, a0);
        a1 = fma2(h0[17], wc.y, a1);
#pragma unroll
        for (int k = 1; k < 8; k++) {
            ws = rs[k];
            wc = rc[k];
            a0 = fma2(h0[2 * k],      ws.x, a0);
            a1 = fma2(h0[16 + 2 * k], wc.x, a1);
            a0 = fma2(h0[2 * k + 1],  ws.y, a0);
            a1 = fma2(h0[17 + 2 * k], wc.y, a1);
        }
        ull a = g2(add2(a0, a1));
        if (jj & 1) oB = fma2(a, cw.w2[jj], oB);
        else        oA = fma2(a, cw.w2[jj], oA);
    }
    ull o = add2(oA, oB);

    float o0, o1;
    upk2(o, o0, o1);
    *reinterpret_cast<float2*>(out + base) = make_float2(o0, o1);
}

extern "C" void kernel_launch(void* const* d_in, const int* in_sizes, int n_in,
                              void* d_out, int out_size) {
    const float* x  = (const float*)d_in[0];
    const float* W0 = (const float*)d_in[1];
    const float* b0 = (const float*)d_in[2];
    const float* W1 = (const float*)d_in[3];
    const float* b1 = (const float*)d_in[4];
    const float* W2 = (const float*)d_in[5];
    const float* b2 = (const float*)d_in[6];
    float* out = (float*)d_out;

    // 1) fold/transform the constant-bank half into staging (device global)
    prep_kernel<<<1, BLK>>>(W1, b1, W2, b2);

    // 2) staging -> constant bank (D2D async memcpy, graph-capturable)
    void* stage_ptr = nullptr;
    cudaGetSymbolAddress(&stage_ptr, g_stage);
    cudaMemcpyToSymbolAsync(cw, stage_ptr, sizeof(CW), 0, cudaMemcpyDeviceToDevice, 0);

    // 3) main kernel (stages SMEM halves itself)
    const int total = T_STEPS * NPTS;       // 4194304 points
    const int threads = total / 2;          // 2 points per thread
    mlpconv_kernel<<<threads / BLK, BLK>>>(x, W0, b0, W1, out);
}

// round 17
// speedup vs baseline: 1.0747x; 1.0402x over previous
#include <cuda_runtime.h>

typedef unsigned long long ull;

static constexpr int T_STEPS = 64;
static constexpr int NSIDE = 256;
static constexpr int NPTS = NSIDE * NSIDE;   // 65536
static constexpr int HID = 32;
static constexpr int BLK = 128;
static constexpr float LOG2E = 1.44269504088896340736f;

// Constant bank (MUST stay <= ~4.6KB: larger footprints miss the const cache
// to L2 -- measured cliff R12 vs R10/R11/R13): SECOND half of W1 (cc 16..31),
// folded biases, W2. 16B-aligned for LDC.128 fetches.
struct CW {
    ull w1b[HID * 16];    // [jj*16 + (cc-16)] = dup(log2e*W1[cc][jj])
    ull b1[HID];          // dup(log2e*(b1[jj] - sum_c W1[c][jj]))
    ull w2[HID];          // dup(W2[jj])
    float b2;             // b2 - sum_j W2[j]
};
__constant__ __align__(16) CW cw;
__device__ __align__(16) CW g_stage;

__device__ __forceinline__ ull dupf(float v) {
    unsigned u = __float_as_uint(v);
    return (ull)u | ((ull)u << 32);
}

__global__ void prep_kernel(const float* __restrict__ W1, const float* __restrict__ b1,
                            const float* __restrict__ W2, const float* __restrict__ b2) {
    const int tid = threadIdx.x;
    for (int i0 = tid; i0 < HID * 16; i0 += BLK) {
        int jj = i0 >> 4, cc = (i0 & 15) + 16;
        g_stage.w1b[i0] = dupf(LOG2E * W1[cc * HID + jj]);
    }
    if (tid < HID) {
        float s = 0.0f;
        for (int c = 0; c < HID; c++) s += W1[c * HID + tid];
        g_stage.b1[tid] = dupf(LOG2E * (b1[tid] - s));
        g_stage.w2[tid] = dupf(W2[tid]);
    }
    if (tid == 0) {
        float s = 0.0f;
        for (int jj = 0; jj < HID; jj++) s += W2[jj];
        g_stage.b2 = b2[0] - s;
    }
}

// ---- packed f32x2 helpers (Blackwell FFMA2 only reachable via PTX) ----
__device__ __forceinline__ ull fma2(ull a, ull b, ull c) {
    ull d;
    asm("fma.rn.f32x2 %0, %1, %2, %3;" : "=l"(d) : "l"(a), "l"(b), "l"(c));
    return d;
}
__device__ __forceinline__ ull mul2(ull a, ull b) {
    ull d;
    asm("mul.rn.f32x2 %0, %1, %2;" : "=l"(d) : "l"(a), "l"(b));
    return d;
}
__device__ __forceinline__ ull add2(ull a, ull b) {
    ull d;
    asm("add.rn.f32x2 %0, %1, %2;" : "=l"(d) : "l"(a), "l"(b));
    return d;
}
__device__ __forceinline__ ull pk2(float lo, float hi) {
    ull r;
    asm("mov.b64 %0, {%1, %2};" : "=l"(r) : "f"(lo), "f"(hi));
    return r;
}
__device__ __forceinline__ void upk2(ull v, float& lo, float& hi) {
    asm("mov.b64 {%0, %1}, %2;" : "=f"(lo), "=f"(hi) : "l"(v));
}
__device__ __forceinline__ float ex2f(float v) {
    float r;
    asm("ex2.approx.f32 %0, %1;" : "=f"(r) : "f"(v));
    return r;
}
// preactivation pre-scaled by log2e:  g(v) = elu(v)+1 = max(v',0)*ln2 + ex2(min(v',0))
__device__ __forceinline__ ull g2(ull v) {
    const float LN2 = 0.69314718055994530942f;
    float a, b; upk2(v, a, b);
    float ea = ex2f(fminf(a, 0.0f));
    float eb = ex2f(fminf(b, 0.0f));
    float ha = fmaf(fmaxf(a, 0.0f), LN2, ea);
    float hb = fmaf(fmaxf(b, 0.0f), LN2, eb);
    return pk2(ha, hb);
}

// 2 consecutive points per thread as ONE f32x2 pair. DUAL-PORT weights:
// layer0 + W1 lower half from SMEM (L1 port, LDS.128), W1 upper half + biases
// from the constant bank (constant port, under the const-cache cliff).
// Layer-1: manual 2x unroll -> two fully independent jj bodies per iteration
// (no predicated accumulate; doubled load->use scheduling window).
__global__ __launch_bounds__(BLK, 4)
void mlpconv_kernel(const float* __restrict__ x,
                    const float* __restrict__ W0, const float* __restrict__ b0,
                    const float* __restrict__ W1,
                    float* __restrict__ out) {
    // sW0r[jj][0..4] = dup(log2e*W0[c][jj]), [5] = dup(log2e*b0[jj]), pad to 8
    __shared__ __align__(16) ull sW0r[HID * 8];
    // sW1a[jj*16+cc] = dup(log2e*W1[cc][jj]) for cc 0..15
    __shared__ __align__(16) ull sW1a[HID * 16];

    const int tid = threadIdx.x;

    for (int i0 = tid; i0 < HID * 16; i0 += BLK) {
        int jj = i0 >> 4, cc = i0 & 15;
        sW1a[i0] = dupf(LOG2E * W1[cc * HID + jj]);
    }
    for (int i0 = tid; i0 < HID * 8; i0 += BLK) {
        int jj = i0 >> 3, c = i0 & 7;
        float v = 0.0f;
        if (c < 5)       v = LOG2E * W0[c * HID + jj];
        else if (c == 5) v = LOG2E * b0[jj];
        sW0r[i0] = dupf(v);
    }
    __syncthreads();

    const int gid = blockIdx.x * BLK + tid;
    const int base = gid * 2;                  // 2 points per thread
    const int t = base >> 16;
    const int p = base & (NPTS - 1);
    const float* xt = x + ((size_t)t << 16);
    const int i = p >> 8;
    const int j = p & 255;                     // even -> pair never crosses a row

    // Stencil (reference's exact wrap semantics)
    const float2 c2 = *reinterpret_cast<const float2*>(xt + p);
    const float2 u2 = *reinterpret_cast<const float2*>(xt + ((p - NSIDE) & (NPTS - 1)));
    const float2 d2 = *reinterpret_cast<const float2*>(xt + ((p + NSIDE) & (NPTS - 1)));
    const float lE = xt[(p - 1) & (NPTS - 1)];
    const float rE = xt[(i << 8) | ((j + 2) & 255)];

    // channel order: l, l2(up), c, r, r2(down); halves = points (0,1)
    const ull pxl = pk2(lE,   c2.x);
    const ull pxu = pk2(u2.x, u2.y);
    const ull pxc = pk2(c2.x, c2.y);
    const ull pxr = pk2(c2.y, rE);
    const ull pxd = pk2(d2.x, d2.y);

    // ---- layer 0: [5] -> [32], SMEM weights, g-activation (2 chains) ----
    ull h0[HID];
#pragma unroll
    for (int jj = 0; jj < HID; jj++) {
        const ulonglong2* r = reinterpret_cast<const ulonglong2*>(sW0r + jj * 8);
        ulonglong2 w01 = r[0];
        ulonglong2 w23 = r[1];
        ulonglong2 w4b = r[2];
        ull a0 = fma2(pxl, w01.x, w4b.y);
        ull a1 = mul2(pxu, w01.y);
        a0 = fma2(pxc, w23.x, a0);
        a1 = fma2(pxr, w23.y, a1);
        a0 = fma2(pxd, w4b.x, a0);
        h0[jj] = g2(add2(a0, a1));
    }

    // ---- layer 1: [32] -> [32], g-activation, fused layer-2 accumulation ----
    // Two jj rows per iteration, fully independent bodies; chain a0/b0 eats
    // SMEM weights (cc 0..15), chain a1/b1 eats constant weights (cc 16..31).
    ull oA = pk2(cw.b2, cw.b2);
    ull oB = pk2(0.0f, 0.0f);
#pragma unroll 2
    for (int jj = 0; jj < HID; jj += 2) {
        const int jB = jj + 1;
        const ulonglong2* rsA = reinterpret_cast<const ulonglong2*>(sW1a + jj * 16);
        const ulonglong2* rsB = reinterpret_cast<const ulonglong2*>(sW1a + jB * 16);
        const ulonglong2* rcA = reinterpret_cast<const ulonglong2*>(cw.w1b + jj * 16);
        const ulonglong2* rcB = reinterpret_cast<const ulonglong2*>(cw.w1b + jB * 16);

        ulonglong2 wsA = rsA[0];
        ulonglong2 wcA = rcA[0];
        ulonglong2 wsB = rsB[0];
        ulonglong2 wcB = rcB[0];
        ull a0 = fma2(h0[0],  wsA.x, cw.b1[jj]);
        ull a1 = mul2(h0[16], wcA.x);
        ull b0_ = fma2(h0[0],  wsB.x, cw.b1[jB]);
        ull b1_ = mul2(h0[16], wcB.x);
        a0  = fma2(h0[1],  wsA.y, a0);
        a1  = fma2(h0[17], wcA.y, a1);
        b0_ = fma2(h0[1],  wsB.y, b0_);
        b1_ = fma2(h0[17], wcB.y, b1_);
#pragma unroll
        for (int k = 1; k < 8; k++) {
            wsA = rsA[k];
            wcA = rcA[k];
            wsB = rsB[k];
            wcB = rcB[k];
            a0  = fma2(h0[2 * k],      wsA.x, a0);
            a1  = fma2(h0[16 + 2 * k], wcA.x, a1);
            b0_ = fma2(h0[2 * k],      wsB.x, b0_);
            b1_ = fma2(h0[16 + 2 * k], wcB.x, b1_);
            a0  = fma2(h0[2 * k + 1],  wsA.y, a0);
            a1  = fma2(h0[17 + 2 * k], wcA.y, a1);
            b0_ = fma2(h0[2 * k + 1],  wsB.y, b0_);
            b1_ = fma2(h0[17 + 2 * k], wcB.y, b1_);
        }
        ull aA = g2(add2(a0, a1));
        ull aB = g2(add2(b0_, b1_));
        oA = fma2(aA, cw.w2[jj], oA);
        oB = fma2(aB, cw.w2[jB], oB);
    }
    ull o = add2(oA, oB);

    float o0, o1;
    upk2(o, o0, o1);
    *reinterpret_cast<float2*>(out + base) = make_float2(o0, o1);
}

extern "C" void kernel_launch(void* const* d_in, const int* in_sizes, int n_in,
                              void* d_out, int out_size) {
    const float* x  = (const float*)d_in[0];
    const float* W0 = (const float*)d_in[1];
    const float* b0 = (const float*)d_in[2];
    const float* W1 = (const float*)d_in[3];
    const float* b1 = (const float*)d_in[4];
    const float* W2 = (const float*)d_in[5];
    const float* b2 = (const float*)d_in[6];
    float* out = (float*)d_out;

    // 1) fold/transform the constant-bank half into staging (device global)
    prep_kernel<<<1, BLK>>>(W1, b1, W2, b2);

    // 2) staging -> constant bank (D2D async memcpy, graph-capturable)
    void* stage_ptr = nullptr;
    cudaGetSymbolAddress(&stage_ptr, g_stage);
    cudaMemcpyToSymbolAsync(cw, stage_ptr, sizeof(CW), 0, cudaMemcpyDeviceToDevice, 0);

    // 3) main kernel (stages SMEM halves itself)
    const int total = T_STEPS * NPTS;       // 4194304 points
    const int threads = total / 2;          // 2 points per thread
    mlpconv_kernel<<<threads / BLK, BLK>>>(x, W0, b0, W1, out);
}